// round 1
// baseline (speedup 1.0000x reference)
#include <cuda_runtime.h>
#include <math.h>

#define NN   40000
#define NE   640000
#define FIN  64
#define FOUT 128
#define NP   12
#define FTOT 768      /* FIN*NP */
#define GC   512      /* 4*FOUT */

// ---------------- device scratch (static, no allocations) ----------------
__device__ float d_deg[NN];
__device__ float d_dinv[NN];
__device__ int   d_counts[NN];
__device__ int   d_cursor[NN];
__device__ int   d_offsets[NN + 1];
__device__ int   d_csr[NE];
__device__ float d_S[NP * NN * FIN];   // [t][n][k]  (~123 MB)
__device__ float d_H[NN * FOUT];
__device__ float d_C[NN * FOUT];
__device__ float d_W1[FIN * GC];       // folded W_x @ W_h_top, 4 gates concat on cols
__device__ float d_W2[FOUT * GC];      // W_h_bottom, 4 gates concat on cols
__device__ float d_bias[GC];
__device__ float d_probs[NP];

struct GateW {
    const float* wx[4];
    const float* bx[4];
    const float* wh[4];
    const float* bh[4];
    const float* att;
};

// ---------------- packed f32x2 helpers (FFMA2) ----------------
__device__ __forceinline__ unsigned long long pk2(float x) {
    unsigned long long r;
    asm("mov.b64 %0, {%1, %1};" : "=l"(r) : "f"(x));
    return r;
}
__device__ __forceinline__ unsigned long long f2fma(unsigned long long a,
                                                    unsigned long long b,
                                                    unsigned long long c) {
    unsigned long long d;
    asm("fma.rn.f32x2 %0, %1, %2, %3;" : "=l"(d) : "l"(a), "l"(b), "l"(c));
    return d;
}
__device__ __forceinline__ float2 up2(unsigned long long v) {
    float2 r;
    asm("mov.b64 {%0, %1}, %2;" : "=f"(r.x), "=f"(r.y) : "l"(v));
    return r;
}

// ---------------- kernels ----------------
__global__ void zero_kernel() {
    int i = blockIdx.x * blockDim.x + threadIdx.x;
    int stride = gridDim.x * blockDim.x;
    for (int idx = i; idx < NN * FOUT; idx += stride) { d_H[idx] = 0.f; d_C[idx] = 0.f; }
    for (int idx = i; idx < NN; idx += stride) { d_deg[idx] = 0.f; d_counts[idx] = 0; d_cursor[idx] = 0; }
}

__global__ void deg_kernel(const int* __restrict__ ei, const float* __restrict__ ew) {
    int i = blockIdx.x * blockDim.x + threadIdx.x;
    int stride = gridDim.x * blockDim.x;
    for (int e = i; e < NE; e += stride) {
        int c = ei[NE + e];
        atomicAdd(&d_deg[c], ew[e]);
        atomicAdd(&d_counts[c], 1);
    }
}

__global__ void dinv_kernel() {
    int i = blockIdx.x * blockDim.x + threadIdx.x;
    int stride = gridDim.x * blockDim.x;
    for (int n = i; n < NN; n += stride)
        d_dinv[n] = rsqrtf(d_deg[n] + 1.0f);   // +1 = self-loop; always > 0
}

__global__ void scan_kernel() {
    __shared__ int temp[1024];
    __shared__ int s_carry;
    int tid = threadIdx.x;
    if (tid == 0) s_carry = 0;
    __syncthreads();
    for (int base = 0; base < NN; base += 1024) {
        int v = (base + tid < NN) ? d_counts[base + tid] : 0;
        temp[tid] = v;
        __syncthreads();
        for (int off = 1; off < 1024; off <<= 1) {
            int tv = (tid >= off) ? temp[tid - off] : 0;
            __syncthreads();
            temp[tid] += tv;
            __syncthreads();
        }
        int c = s_carry;
        if (base + tid < NN) d_offsets[base + tid] = c + temp[tid] - v;  // exclusive
        __syncthreads();
        if (tid == 0) s_carry = c + temp[1023];
        __syncthreads();
    }
    if (tid == 0) d_offsets[NN] = s_carry;
}

__global__ void fill_kernel(const int* __restrict__ ei) {
    int i = blockIdx.x * blockDim.x + threadIdx.x;
    int stride = gridDim.x * blockDim.x;
    for (int e = i; e < NE; e += stride) {
        int c = ei[NE + e];
        int p = atomicAdd(&d_cursor[c], 1);
        d_csr[d_offsets[c] + p] = e;
    }
}

// W1[k][g*128+j] = sum_m Wx_g[k][m] * Wh_g[m][j]   (top half of Wh)
__global__ void prep_w1_kernel(GateW gw) {
    int k = blockIdx.x;           // 0..63
    int c = threadIdx.x;          // 0..511
    int g = c >> 7, j = c & 127;
    const float* wx = gw.wx[g];
    const float* wh = gw.wh[g];
    float acc = 0.f;
#pragma unroll 8
    for (int m = 0; m < FOUT; m++)
        acc += wx[k * FOUT + m] * wh[m * FOUT + j];
    d_W1[k * GC + c] = acc;
}

__global__ void prep_w2_kernel(GateW gw) {
    int k = blockIdx.x;           // 0..127
    int c = threadIdx.x;          // 0..511
    int g = c >> 7, j = c & 127;
    d_W2[k * GC + c] = gw.wh[g][(FOUT + k) * FOUT + j];
}

__global__ void prep_bias_kernel(GateW gw) {
    int c = threadIdx.x;          // 0..511
    int g = c >> 7, j = c & 127;
    float acc = gw.bh[g][j];
    for (int m = 0; m < FOUT; m++)
        acc += gw.bx[g][m] * gw.wh[g][m * FOUT + j];
    d_bias[c] = acc;
    if (c == 0) {
        float a[NP], mx = -1e30f, s = 0.f;
        for (int t = 0; t < NP; t++) { a[t] = gw.att[t]; mx = fmaxf(mx, a[t]); }
        for (int t = 0; t < NP; t++) { a[t] = expf(a[t] - mx); s += a[t]; }
        for (int t = 0; t < NP; t++) d_probs[t] = a[t] / s;
    }
}

// Gather-SpMM: S[t][n][fin] = sum over incoming edges + self loop, one block per node.
__global__ __launch_bounds__(768) void spmm_kernel(const float* __restrict__ X,
                                                   const int* __restrict__ ei,
                                                   const float* __restrict__ ew) {
    __shared__ int   srow[64];
    __shared__ float snrm[64];
    __shared__ float sval[FTOT];
    int n = blockIdx.x;
    int tid = threadIdx.x;          // 0..767 == (fin, t) flat in X layout
    float dn = d_dinv[n];
    float acc = dn * dn * X[n * FTOT + tid];   // self loop, weight 1
    int beg = d_offsets[n], end = d_offsets[n + 1];
    for (int eb = beg; eb < end; eb += 64) {
        int cnt = min(64, end - eb);
        if (tid < cnt) {
            int e = d_csr[eb + tid];
            int r = ei[e];                     // source node
            srow[tid] = r;
            snrm[tid] = d_dinv[r] * ew[e] * dn;
        }
        __syncthreads();
        for (int i = 0; i < cnt; i++)
            acc += snrm[i] * X[srow[i] * FTOT + tid];
        __syncthreads();
    }
    sval[tid] = acc;
    __syncthreads();
    // transpose write: thread -> (t = tid/64, fin = tid%64), fully coalesced
    int t = tid >> 6, f = tid & 63;
    d_S[t * (NN * FIN) + n * FIN + f] = sval[f * NP + t];
}

// Fused per-period step: Z = [S_t | H] @ [W1; W2] + bias, then LSTM elementwise.
// Block: 16 nodes x all 512 gate columns, K = 192 in 12 tiles of 16.
__global__ __launch_bounds__(256) void step_kernel(int t, float* __restrict__ Hacc) {
    __shared__ __align__(16) float As[16][20];     // [kk][node], padded
    __shared__ __align__(16) float Bs[16 * GC];    // 32 KB, reused as Z staging
    int tid = threadIdx.x;
    int tx = tid & 63;       // 8 cols each
    int ty = tid >> 6;       // 4 nodes each
    int node0 = blockIdx.x * 16;

    unsigned long long acc[4][4];
#pragma unroll
    for (int i = 0; i < 4; i++)
#pragma unroll
        for (int j = 0; j < 4; j++) acc[i][j] = 0ull;

    const float* Sbase = d_S + t * (NN * FIN) + node0 * FIN;
    const float* Hbase = d_H + node0 * FOUT;

    for (int kt = 0; kt < 12; kt++) {
        int k0 = kt * 16;
        {   // A tile: coalesced 16-float runs per node
            int nd = tid >> 4, kk = tid & 15;
            float v = (k0 < FIN) ? Sbase[nd * FIN + k0 + kk]
                                 : Hbase[nd * FOUT + (k0 - FIN) + kk];
            As[kk][nd] = v;
        }
        {   // B tile: 16x512 contiguous floats
            const float4* Bsrc = (const float4*)((k0 < FIN) ? (d_W1 + k0 * GC)
                                                            : (d_W2 + (k0 - FIN) * GC));
            float4* Bdst = (float4*)Bs;
#pragma unroll
            for (int i = 0; i < 8; i++) Bdst[i * 256 + tid] = Bsrc[i * 256 + tid];
        }
        __syncthreads();

#pragma unroll
        for (int kk = 0; kk < 16; kk++) {
            float4 a4 = *(const float4*)&As[kk][ty * 4];
            const ulonglong2* bp = (const ulonglong2*)&Bs[kk * GC + tx * 8];
            ulonglong2 bb0 = bp[0], bb1 = bp[1];
            unsigned long long bb[4] = {bb0.x, bb0.y, bb1.x, bb1.y};
            const float* af = (const float*)&a4;
#pragma unroll
            for (int i = 0; i < 4; i++) {
                unsigned long long aa = pk2(af[i]);
#pragma unroll
                for (int j = 0; j < 4; j++)
                    acc[i][j] = f2fma(aa, bb[j], acc[i][j]);
            }
        }
        __syncthreads();
    }

    float4 bias0 = *(const float4*)&d_bias[tx * 8];
    float4 bias1 = *(const float4*)&d_bias[tx * 8 + 4];

    // unpack + bias, stage Z into Bs
#pragma unroll
    for (int i = 0; i < 4; i++) {
        float2 z0 = up2(acc[i][0]), z1 = up2(acc[i][1]);
        float2 z2 = up2(acc[i][2]), z3 = up2(acc[i][3]);
        float4 w0 = make_float4(z0.x + bias0.x, z0.y + bias0.y, z1.x + bias0.z, z1.y + bias0.w);
        float4 w1 = make_float4(z2.x + bias1.x, z2.y + bias1.y, z3.x + bias1.z, z3.y + bias1.w);
        float4* zp = (float4*)&Bs[(ty * 4 + i) * GC + tx * 8];
        zp[0] = w0; zp[1] = w1;
    }
    __syncthreads();

    float p = d_probs[t];
#pragma unroll
    for (int r = 0; r < 8; r++) {
        int it = r * 256 + tid;        // 0..2047
        int nd = it >> 7;              // node in tile
        int j  = it & 127;             // feature
        float zi = Bs[nd * GC + j];
        float zf = Bs[nd * GC + 128 + j];
        float zc = Bs[nd * GC + 256 + j];
        float zo = Bs[nd * GC + 384 + j];
        int gidx = (node0 + nd) * FOUT + j;
        float I  = 1.f / (1.f + __expf(-zi));
        float F  = 1.f / (1.f + __expf(-zf));
        float Ct = tanhf(zc);
        float O  = 1.f / (1.f + __expf(-zo));
        float cn = F * d_C[gidx] + I * Ct;
        float h  = O * tanhf(cn);
        d_C[gidx] = cn;
        d_H[gidx] = h;
        if (t == 0) Hacc[gidx] = p * h;
        else        Hacc[gidx] += p * h;
    }
}

// ---------------- launch ----------------
extern "C" void kernel_launch(void* const* d_in, const int* in_sizes, int n_in,
                              void* d_out, int out_size) {
    const float* X   = (const float*)d_in[0];
    const int*   ei  = (const int*)d_in[1];
    const float* ew  = (const float*)d_in[2];
    const float* att = (const float*)d_in[3];
    GateW gw;
    for (int g = 0; g < 4; g++) {
        gw.wx[g] = (const float*)d_in[4 + 4 * g];
        gw.bx[g] = (const float*)d_in[5 + 4 * g];
        gw.wh[g] = (const float*)d_in[6 + 4 * g];
        gw.bh[g] = (const float*)d_in[7 + 4 * g];
    }
    gw.att = att;
    float* out = (float*)d_out;

    zero_kernel<<<512, 256>>>();
    deg_kernel<<<640, 256>>>(ei, ew);
    dinv_kernel<<<160, 256>>>();
    scan_kernel<<<1, 1024>>>();
    fill_kernel<<<640, 256>>>(ei);
    prep_w1_kernel<<<64, 512>>>(gw);
    prep_w2_kernel<<<128, 512>>>(gw);
    prep_bias_kernel<<<1, 512>>>(gw);
    spmm_kernel<<<NN, 768>>>(X, ei, ew);
    for (int t = 0; t < NP; t++)
        step_kernel<<<NN / 16, 256>>>(t, out);
}